// round 3
// baseline (speedup 1.0000x reference)
#include <cuda_runtime.h>

// ---------------------------------------------------------------------------
// MultiHeadSelfAttention: B=4, S=2048, D=1024, H=16, Dh=64, fp32, causal.
//
// Stage 1: Q = x @ Wq^T, K = x @ Wk^T, V = x @ Wv^T   (NT SGEMM 128x128x8 DB)
// Stage 2: flash attention (online softmax, causal), per (b,h), 64x64 tiles
// Stage 3: out = A @ Wo^T
// ---------------------------------------------------------------------------

#define SEQ 2048
#define BATCH 4
#define DMODEL 1024
#define NHEADS 16
#define HDIM 64
#define MTOT (BATCH * SEQ)          // 8192

// Scratch: Q, K, V, A  (each 8192x1024 fp32 = 32 MB)
__device__ float g_scratch[4ull * MTOT * DMODEL];

// ---------------------------------------------------------------------------
// NT SGEMM: C[m,n] = sum_k A[m*K+k] * B[n*K+k]
// 128x128 tile, 8-deep k-slab, double-buffered smem, 256 threads, 8x8/thread.
// Requires M%128==0, N%128==0, K%8==0 (true here).
// ---------------------------------------------------------------------------
#define GTP 132   // padded tile stride

__global__ __launch_bounds__(256) void gemm_nt_kernel(
    const float* __restrict__ A, const float* __restrict__ B, float* __restrict__ C,
    int M, int N, int K)
{
    __shared__ float As[2][8][GTP];   // [buf][k][m]
    __shared__ float Bs[2][8][GTP];   // [buf][k][n]

    const int bm = blockIdx.y * 128;
    const int bn = blockIdx.x * 128;
    const int tid = threadIdx.x;
    const int tx = tid & 15;          // col group
    const int ty = tid >> 4;          // row group

    // loader mapping: each thread loads one float4 of A and one of B per slab
    const int lrow = tid >> 1;            // 0..127
    const int lk   = (tid & 1) << 2;      // 0 or 4

    const float* Aptr = A + (size_t)(bm + lrow) * K + lk;
    const float* Bptr = B + (size_t)(bn + lrow) * K + lk;

    // preload slab 0
    {
        float4 a4 = *(const float4*)Aptr;
        float4 b4 = *(const float4*)Bptr;
        As[0][lk + 0][lrow] = a4.x; As[0][lk + 1][lrow] = a4.y;
        As[0][lk + 2][lrow] = a4.z; As[0][lk + 3][lrow] = a4.w;
        Bs[0][lk + 0][lrow] = b4.x; Bs[0][lk + 1][lrow] = b4.y;
        Bs[0][lk + 2][lrow] = b4.z; Bs[0][lk + 3][lrow] = b4.w;
    }
    __syncthreads();

    float acc[8][8];
#pragma unroll
    for (int i = 0; i < 8; i++)
#pragma unroll
        for (int j = 0; j < 8; j++) acc[i][j] = 0.0f;

    int buf = 0;
    for (int k0 = 8; k0 <= K; k0 += 8) {
        float4 na, nb4;
        const bool more = (k0 < K);
        if (more) {
            na  = *(const float4*)(Aptr + k0);
            nb4 = *(const float4*)(Bptr + k0);
        }

#pragma unroll
        for (int kk = 0; kk < 8; kk++) {
            float4 a0 = *(const float4*)&As[buf][kk][ty << 2];
            float4 a1 = *(const float4*)&As[buf][kk][(ty << 2) + 64];
            float4 b0 = *(const float4*)&Bs[buf][kk][tx << 2];
            float4 b1 = *(const float4*)&Bs[buf][kk][(tx << 2) + 64];
            float ar[8] = {a0.x, a0.y, a0.z, a0.w, a1.x, a1.y, a1.z, a1.w};
            float br[8] = {b0.x, b0.y, b0.z, b0.w, b1.x, b1.y, b1.z, b1.w};
#pragma unroll
            for (int i = 0; i < 8; i++)
#pragma unroll
                for (int j = 0; j < 8; j++) acc[i][j] += ar[i] * br[j];
        }

        if (more) {
            int nbuf = buf ^ 1;
            As[nbuf][lk + 0][lrow] = na.x;  As[nbuf][lk + 1][lrow] = na.y;
            As[nbuf][lk + 2][lrow] = na.z;  As[nbuf][lk + 3][lrow] = na.w;
            Bs[nbuf][lk + 0][lrow] = nb4.x; Bs[nbuf][lk + 1][lrow] = nb4.y;
            Bs[nbuf][lk + 2][lrow] = nb4.z; Bs[nbuf][lk + 3][lrow] = nb4.w;
            __syncthreads();
            buf = nbuf;
        }
    }

    // write back: rows ty*4 + {0..3, 64..67}, cols tx*4 + {0..3, 64..67}
#pragma unroll
    for (int half = 0; half < 2; half++) {
#pragma unroll
        for (int i = 0; i < 4; i++) {
            int r = bm + (ty << 2) + half * 64 + i;
            int ii = half * 4 + i;
            float4 v0 = make_float4(acc[ii][0], acc[ii][1], acc[ii][2], acc[ii][3]);
            float4 v1 = make_float4(acc[ii][4], acc[ii][5], acc[ii][6], acc[ii][7]);
            *(float4*)&C[(size_t)r * N + bn + (tx << 2)]      = v0;
            *(float4*)&C[(size_t)r * N + bn + (tx << 2) + 64] = v1;
        }
    }
}

// ---------------------------------------------------------------------------
// Flash attention, fp32, causal.
// grid: (SEQ/64, BATCH*NHEADS). 256 threads. 64 queries x 64 keys per tile.
// ---------------------------------------------------------------------------
#define SMP 68   // padded tile stride

__global__ __launch_bounds__(256) void flash_kernel(
    const float* __restrict__ Q, const float* __restrict__ K,
    const float* __restrict__ V, float* __restrict__ O)
{
    extern __shared__ float sm[];
    float* Qs  = sm;                    // 64*68
    float* KPs = sm + 64 * SMP;         // 64*68
    float* Vs  = sm + 2 * 64 * SMP;     // 64*68
    float* red = sm + 3 * 64 * SMP;     // 64*17

    const int tid = threadIdx.x;
    const int tx = tid & 15;            // key cols tx*4..
    const int ty = tid >> 4;            // query rows ty*4..
    const int qt = blockIdx.x;
    const int q0 = qt * 64;
    const int bh = blockIdx.y;
    const int b = bh >> 4, h = bh & 15;

    const int base = (b * SEQ) * DMODEL + h * HDIM;
    const float* Qp = Q + base;
    const float* Kp = K + base;
    const float* Vp = V + base;

    // Load Q tile, transposed: Qs[d][r]
#pragma unroll
    for (int i = 0; i < 16; i++) {
        int idx = tid + i * 256;        // 0..4095
        int d = idx & 63;
        int r = idx >> 6;
        Qs[d * SMP + r] = Qp[(q0 + r) * DMODEL + d];
    }

    float m_i[4], l_i[4], o[4][4];
#pragma unroll
    for (int i = 0; i < 4; i++) {
        m_i[i] = -1e30f; l_i[i] = 0.0f;
#pragma unroll
        for (int j = 0; j < 4; j++) o[i][j] = 0.0f;
    }

    for (int kt = 0; kt <= qt; kt++) {
        const int k0 = kt * 64;
        __syncthreads();   // previous tile fully consumed (also covers initial Q load)

        // Load K tile transposed (KPs[d][c]) and V tile (Vs[c][j])
#pragma unroll
        for (int i = 0; i < 16; i++) {
            int idx = tid + i * 256;
            int d = idx & 63;
            int c = idx >> 6;
            KPs[d * SMP + c] = Kp[(k0 + c) * DMODEL + d];
            Vs[c * SMP + d]  = Vp[(k0 + c) * DMODEL + d];
        }
        __syncthreads();

        // S = Q K^T  (4x4 per thread)
        float s[4][4];
#pragma unroll
        for (int i = 0; i < 4; i++)
#pragma unroll
            for (int j = 0; j < 4; j++) s[i][j] = 0.0f;

#pragma unroll 16
        for (int d = 0; d < 64; d++) {
            float4 a  = *(const float4*)&Qs[d * SMP + (ty << 2)];
            float4 bk = *(const float4*)&KPs[d * SMP + (tx << 2)];
            s[0][0] += a.x * bk.x; s[0][1] += a.x * bk.y; s[0][2] += a.x * bk.z; s[0][3] += a.x * bk.w;
            s[1][0] += a.y * bk.x; s[1][1] += a.y * bk.y; s[1][2] += a.y * bk.z; s[1][3] += a.y * bk.w;
            s[2][0] += a.z * bk.x; s[2][1] += a.z * bk.y; s[2][2] += a.z * bk.z; s[2][3] += a.z * bk.w;
            s[3][0] += a.w * bk.x; s[3][1] += a.w * bk.y; s[3][2] += a.w * bk.z; s[3][3] += a.w * bk.w;
        }

        const float scale = 0.125f;     // 1/sqrt(64)
        if (kt == qt) {
#pragma unroll
            for (int i = 0; i < 4; i++) {
                int r = q0 + (ty << 2) + i;
#pragma unroll
                for (int j = 0; j < 4; j++) {
                    int c = k0 + (tx << 2) + j;
                    s[i][j] = (c <= r) ? s[i][j] * scale : -1e30f;
                }
            }
        } else {
#pragma unroll
            for (int i = 0; i < 4; i++)
#pragma unroll
                for (int j = 0; j < 4; j++) s[i][j] *= scale;
        }

        // Row max (partial) -> red
#pragma unroll
        for (int i = 0; i < 4; i++) {
            float rm = fmaxf(fmaxf(s[i][0], s[i][1]), fmaxf(s[i][2], s[i][3]));
            red[((ty << 2) + i) * 17 + tx] = rm;
        }
        __syncthreads();

        float alpha[4], rsum[4];
        float p[4][4];
#pragma unroll
        for (int i = 0; i < 4; i++) {
            int r = (ty << 2) + i;
            float t = m_i[i];
#pragma unroll
            for (int k2 = 0; k2 < 16; k2++) t = fmaxf(t, red[r * 17 + k2]);
            alpha[i] = __expf(m_i[i] - t);
            m_i[i] = t;
            rsum[i] = 0.0f;
#pragma unroll
            for (int j = 0; j < 4; j++) {
                p[i][j] = __expf(s[i][j] - t);
                rsum[i] += p[i][j];
            }
        }
        __syncthreads();   // red(max) reads done; KPs(S) reads done

        // Write partial row sums and P^T (into the K buffer)
#pragma unroll
        for (int i = 0; i < 4; i++) {
            red[((ty << 2) + i) * 17 + tx] = rsum[i];
#pragma unroll
            for (int j = 0; j < 4; j++)
                KPs[((tx << 2) + j) * SMP + (ty << 2) + i] = p[i][j];
        }
        __syncthreads();

        // Rescale accumulators, fold in row sums
#pragma unroll
        for (int i = 0; i < 4; i++) {
            int r = (ty << 2) + i;
            float t = 0.0f;
#pragma unroll
            for (int k2 = 0; k2 < 16; k2++) t += red[r * 17 + k2];
            l_i[i] = l_i[i] * alpha[i] + t;
#pragma unroll
            for (int j = 0; j < 4; j++) o[i][j] *= alpha[i];
        }

        // O += P V   (P^T stored in KPs[c][r], V in Vs[c][j])
#pragma unroll 16
        for (int c = 0; c < 64; c++) {
            float4 pa = *(const float4*)&KPs[c * SMP + (ty << 2)];
            float4 vb = *(const float4*)&Vs[c * SMP + (tx << 2)];
            o[0][0] += pa.x * vb.x; o[0][1] += pa.x * vb.y; o[0][2] += pa.x * vb.z; o[0][3] += pa.x * vb.w;
            o[1][0] += pa.y * vb.x; o[1][1] += pa.y * vb.y; o[1][2] += pa.y * vb.z; o[1][3] += pa.y * vb.w;
            o[2][0] += pa.z * vb.x; o[2][1] += pa.z * vb.y; o[2][2] += pa.z * vb.z; o[2][3] += pa.z * vb.w;
            o[3][0] += pa.w * vb.x; o[3][1] += pa.w * vb.y; o[3][2] += pa.w * vb.z; o[3][3] += pa.w * vb.w;
        }
    }

    // Normalize + write out
#pragma unroll
    for (int i = 0; i < 4; i++) {
        float inv = 1.0f / l_i[i];
        float4 v = make_float4(o[i][0] * inv, o[i][1] * inv, o[i][2] * inv, o[i][3] * inv);
        int r = q0 + (ty << 2) + i;
        *(float4*)&O[(b * SEQ + r) * DMODEL + h * HDIM + (tx << 2)] = v;
    }
}

// ---------------------------------------------------------------------------
// Launch
// ---------------------------------------------------------------------------
extern "C" void kernel_launch(void* const* d_in, const int* in_sizes, int n_in,
                              void* d_out, int out_size)
{
    const float* x  = (const float*)d_in[0];
    const float* Wq = (const float*)d_in[1];
    const float* Wk = (const float*)d_in[2];
    const float* Wv = (const float*)d_in[3];
    const float* Wo = (const float*)d_in[4];
    float* out = (float*)d_out;

    float* scratch = nullptr;
    cudaGetSymbolAddress((void**)&scratch, g_scratch);
    const int PLANE = MTOT * DMODEL;      // 8388608
    float* Qb = scratch;
    float* Kb = scratch + PLANE;
    float* Vb = scratch + 2 * PLANE;
    float* Ab = scratch + 3 * (size_t)PLANE;

    dim3 ggrid(DMODEL / 128, MTOT / 128);   // (8, 64)
    gemm_nt_kernel<<<ggrid, 256>>>(x, Wq, Qb, MTOT, DMODEL, DMODEL);
    gemm_nt_kernel<<<ggrid, 256>>>(x, Wk, Kb, MTOT, DMODEL, DMODEL);
    gemm_nt_kernel<<<ggrid, 256>>>(x, Wv, Vb, MTOT, DMODEL, DMODEL);

    int smem_bytes = (3 * 64 * SMP + 64 * 17) * (int)sizeof(float);  // 56576
    cudaFuncSetAttribute(flash_kernel, cudaFuncAttributeMaxDynamicSharedMemorySize, smem_bytes);
    flash_kernel<<<dim3(SEQ / 64, BATCH * NHEADS), 256, smem_bytes>>>(Qb, Kb, Vb, Ab);

    gemm_nt_kernel<<<ggrid, 256>>>(Ab, Wo, out, MTOT, DMODEL, DMODEL);
}

// round 4
// speedup vs baseline: 1.0557x; 1.0557x over previous
#include <cuda_runtime.h>
#include <cstdint>

// ---------------------------------------------------------------------------
// MultiHeadSelfAttention: B=4, S=2048, D=1024, H=16, Dh=64, fp32, causal.
//
// Stage 1: Q,K,V projections — 3xTF32 tensor-core NT GEMM (mma.sync m16n8k8)
// Stage 2: flash attention (online softmax, causal), fp32, 64x64 tiles
// Stage 3: out = A @ Wo^T — same 3xTF32 GEMM
// ---------------------------------------------------------------------------

#define SEQ 2048
#define BATCH 4
#define DMODEL 1024
#define NHEADS 16
#define HDIM 64
#define MTOT (BATCH * SEQ)          // 8192

// Scratch: Q, K, V, A  (each 8192x1024 fp32 = 32 MB)
__device__ float g_scratch[4ull * MTOT * DMODEL];

// ---------------------------------------------------------------------------
// 3xTF32 helpers
// ---------------------------------------------------------------------------
__device__ __forceinline__ void split_tf32(float x, uint32_t& hi, uint32_t& lo) {
    uint32_t h;
    asm("cvt.rna.tf32.f32 %0, %1;" : "=r"(h) : "f"(x));
    float r = x - __uint_as_float(h);
    asm("cvt.rna.tf32.f32 %0, %1;" : "=r"(lo) : "f"(r));
    hi = h;
}

__device__ __forceinline__ void mma_tf32(float* d, const uint32_t* a, const uint32_t* b) {
    asm volatile(
        "mma.sync.aligned.m16n8k8.row.col.f32.tf32.tf32.f32 "
        "{%0,%1,%2,%3}, {%4,%5,%6,%7}, {%8,%9}, {%0,%1,%2,%3};"
        : "+f"(d[0]), "+f"(d[1]), "+f"(d[2]), "+f"(d[3])
        : "r"(a[0]), "r"(a[1]), "r"(a[2]), "r"(a[3]), "r"(b[0]), "r"(b[1]));
}

// ---------------------------------------------------------------------------
// NT GEMM via 3xTF32: C[m,n] = sum_k A[m*K+k] * B[n*K+k]
// 128x128 tile, k-slab 16 double-buffered (fp32 in smem, split at frag load).
// 256 threads = 8 warps (2m x 4n), warp tile 64x32, mma m16n8k8.
// Requires M%128==0, N%128==0, K%16==0.
// smem stride 20 floats -> conflict-free fragment LDS (g*20 mod 32 distinct).
// ---------------------------------------------------------------------------
#define KS 16
#define SSTR 20   // smem row stride in floats

__global__ __launch_bounds__(256, 1) void gemm_nt_tf32_kernel(
    const float* __restrict__ A, const float* __restrict__ B, float* __restrict__ C,
    int M, int N, int K)
{
    __shared__ float As[2][128 * SSTR];
    __shared__ float Bs[2][128 * SSTR];

    const int bm = blockIdx.y * 128;
    const int bn = blockIdx.x * 128;
    const int tid = threadIdx.x;
    const int warp = tid >> 5;
    const int lane = tid & 31;
    const int g = lane >> 2;         // groupID
    const int t = lane & 3;          // threadID_in_group
    const int wm = (warp & 1) * 64;  // warp m offset within tile
    const int wn = (warp >> 1) * 32; // warp n offset within tile

    // loader mapping: thread -> rows (lr, lr+64), 4 floats at col lc
    const int lr = tid >> 2;          // 0..63
    const int lc = (tid & 3) * 4;     // 0,4,8,12

    const float* Aptr0 = A + (size_t)(bm + lr) * K + lc;
    const float* Aptr1 = A + (size_t)(bm + lr + 64) * K + lc;
    const float* Bptr0 = B + (size_t)(bn + lr) * K + lc;
    const float* Bptr1 = B + (size_t)(bn + lr + 64) * K + lc;

    // preload slab 0
    {
        float4 a0 = *(const float4*)Aptr0;
        float4 a1 = *(const float4*)Aptr1;
        float4 b0 = *(const float4*)Bptr0;
        float4 b1 = *(const float4*)Bptr1;
        *(float4*)&As[0][lr * SSTR + lc]        = a0;
        *(float4*)&As[0][(lr + 64) * SSTR + lc] = a1;
        *(float4*)&Bs[0][lr * SSTR + lc]        = b0;
        *(float4*)&Bs[0][(lr + 64) * SSTR + lc] = b1;
    }
    __syncthreads();

    float acc[4][4][4];   // [mt][nt][reg]
#pragma unroll
    for (int mt = 0; mt < 4; mt++)
#pragma unroll
        for (int nt = 0; nt < 4; nt++)
#pragma unroll
            for (int r = 0; r < 4; r++) acc[mt][nt][r] = 0.0f;

    int buf = 0;
    for (int k0 = KS; k0 <= K; k0 += KS) {
        const bool more = (k0 < K);
        float4 na0, na1, nb0, nb1;
        if (more) {
            na0 = *(const float4*)(Aptr0 + k0);
            na1 = *(const float4*)(Aptr1 + k0);
            nb0 = *(const float4*)(Bptr0 + k0);
            nb1 = *(const float4*)(Bptr1 + k0);
        }

        const float* Ab = As[buf];
        const float* Bb = Bs[buf];

#pragma unroll
        for (int ks = 0; ks < KS; ks += 8) {
            // --- load + split A fragments: 4 m-tiles x 4 regs ---
            uint32_t ah[4][4], al[4][4];
#pragma unroll
            for (int mt = 0; mt < 4; mt++) {
                int m0 = wm + mt * 16 + g;
                int kk = ks + t;
                split_tf32(Ab[m0 * SSTR + kk],           ah[mt][0], al[mt][0]);
                split_tf32(Ab[(m0 + 8) * SSTR + kk],     ah[mt][1], al[mt][1]);
                split_tf32(Ab[m0 * SSTR + kk + 4],       ah[mt][2], al[mt][2]);
                split_tf32(Ab[(m0 + 8) * SSTR + kk + 4], ah[mt][3], al[mt][3]);
            }
            // --- load + split B fragments: 4 n-tiles x 2 regs ---
            uint32_t bh[4][2], bl[4][2];
#pragma unroll
            for (int nt = 0; nt < 4; nt++) {
                int n0 = wn + nt * 8 + g;
                split_tf32(Bb[n0 * SSTR + ks + t],     bh[nt][0], bl[nt][0]);
                split_tf32(Bb[n0 * SSTR + ks + t + 4], bh[nt][1], bl[nt][1]);
            }
            // --- 3xTF32 MMAs ---
#pragma unroll
            for (int mt = 0; mt < 4; mt++)
#pragma unroll
                for (int nt = 0; nt < 4; nt++) {
                    mma_tf32(acc[mt][nt], ah[mt], bh[nt]);
                    mma_tf32(acc[mt][nt], ah[mt], bl[nt]);
                    mma_tf32(acc[mt][nt], al[mt], bh[nt]);
                }
        }

        if (more) {
            int nbuf = buf ^ 1;
            *(float4*)&As[nbuf][lr * SSTR + lc]        = na0;
            *(float4*)&As[nbuf][(lr + 64) * SSTR + lc] = na1;
            *(float4*)&Bs[nbuf][lr * SSTR + lc]        = nb0;
            *(float4*)&Bs[nbuf][(lr + 64) * SSTR + lc] = nb1;
            __syncthreads();
            buf = nbuf;
        }
    }

    // epilogue: d0:(g,2t) d1:(g,2t+1) d2:(g+8,2t) d3:(g+8,2t+1)
#pragma unroll
    for (int mt = 0; mt < 4; mt++) {
#pragma unroll
        for (int nt = 0; nt < 4; nt++) {
            int m0 = bm + wm + mt * 16 + g;
            int n0 = bn + wn + nt * 8 + 2 * t;
            *(float2*)&C[(size_t)m0 * N + n0]       = make_float2(acc[mt][nt][0], acc[mt][nt][1]);
            *(float2*)&C[(size_t)(m0 + 8) * N + n0] = make_float2(acc[mt][nt][2], acc[mt][nt][3]);
        }
    }
}

// ---------------------------------------------------------------------------
// Flash attention, fp32, causal. (unchanged from R3 baseline)
// grid: (SEQ/64, BATCH*NHEADS). 256 threads. 64 queries x 64 keys per tile.
// ---------------------------------------------------------------------------
#define SMP 68   // padded tile stride

__global__ __launch_bounds__(256) void flash_kernel(
    const float* __restrict__ Q, const float* __restrict__ K,
    const float* __restrict__ V, float* __restrict__ O)
{
    extern __shared__ float sm[];
    float* Qs  = sm;                    // 64*68
    float* KPs = sm + 64 * SMP;         // 64*68
    float* Vs  = sm + 2 * 64 * SMP;     // 64*68
    float* red = sm + 3 * 64 * SMP;     // 64*17

    const int tid = threadIdx.x;
    const int tx = tid & 15;            // key cols tx*4..
    const int ty = tid >> 4;            // query rows ty*4..
    const int qt = blockIdx.x;
    const int q0 = qt * 64;
    const int bh = blockIdx.y;
    const int b = bh >> 4, h = bh & 15;

    const int base = (b * SEQ) * DMODEL + h * HDIM;
    const float* Qp = Q + base;
    const float* Kp = K + base;
    const float* Vp = V + base;

    // Load Q tile, transposed: Qs[d][r]
#pragma unroll
    for (int i = 0; i < 16; i++) {
        int idx = tid + i * 256;        // 0..4095
        int d = idx & 63;
        int r = idx >> 6;
        Qs[d * SMP + r] = Qp[(q0 + r) * DMODEL + d];
    }

    float m_i[4], l_i[4], o[4][4];
#pragma unroll
    for (int i = 0; i < 4; i++) {
        m_i[i] = -1e30f; l_i[i] = 0.0f;
#pragma unroll
        for (int j = 0; j < 4; j++) o[i][j] = 0.0f;
    }

    for (int kt = 0; kt <= qt; kt++) {
        const int k0 = kt * 64;
        __syncthreads();   // previous tile fully consumed (also covers initial Q load)

        // Load K tile transposed (KPs[d][c]) and V tile (Vs[c][j])
#pragma unroll
        for (int i = 0; i < 16; i++) {
            int idx = tid + i * 256;
            int d = idx & 63;
            int c = idx >> 6;
            KPs[d * SMP + c] = Kp[(k0 + c) * DMODEL + d];
            Vs[c * SMP + d]  = Vp[(k0 + c) * DMODEL + d];
        }
        __syncthreads();

        // S = Q K^T  (4x4 per thread)
        float s[4][4];
#pragma unroll
        for (int i = 0; i < 4; i++)
#pragma unroll
            for (int j = 0; j < 4; j++) s[i][j] = 0.0f;

#pragma unroll 16
        for (int d = 0; d < 64; d++) {
            float4 a  = *(const float4*)&Qs[d * SMP + (ty << 2)];
            float4 bk = *(const float4*)&KPs[d * SMP + (tx << 2)];
            s[0][0] += a.x * bk.x; s[0][1] += a.x * bk.y; s[0][2] += a.x * bk.z; s[0][3] += a.x * bk.w;
            s[1][0] += a.y * bk.x; s[1][1] += a.y * bk.y; s[1][2] += a.y * bk.z; s[1][3] += a.y * bk.w;
            s[2][0] += a.z * bk.x; s[2][1] += a.z * bk.y; s[2][2] += a.z * bk.z; s[2][3] += a.z * bk.w;
            s[3][0] += a.w * bk.x; s[3][1] += a.w * bk.y; s[3][2] += a.w * bk.z; s[3][3] += a.w * bk.w;
        }

        const float scale = 0.125f;     // 1/sqrt(64)
        if (kt == qt) {
#pragma unroll
            for (int i = 0; i < 4; i++) {
                int r = q0 + (ty << 2) + i;
#pragma unroll
                for (int j = 0; j < 4; j++) {
                    int c = k0 + (tx << 2) + j;
                    s[i][j] = (c <= r) ? s[i][j] * scale : -1e30f;
                }
            }
        } else {
#pragma unroll
            for (int i = 0; i < 4; i++)
#pragma unroll
                for (int j = 0; j < 4; j++) s[i][j] *= scale;
        }

        // Row max (partial) -> red
#pragma unroll
        for (int i = 0; i < 4; i++) {
            float rm = fmaxf(fmaxf(s[i][0], s[i][1]), fmaxf(s[i][2], s[i][3]));
            red[((ty << 2) + i) * 17 + tx] = rm;
        }
        __syncthreads();

        float alpha[4], rsum[4];
        float p[4][4];
#pragma unroll
        for (int i = 0; i < 4; i++) {
            int r = (ty << 2) + i;
            float t = m_i[i];
#pragma unroll
            for (int k2 = 0; k2 < 16; k2++) t = fmaxf(t, red[r * 17 + k2]);
            alpha[i] = __expf(m_i[i] - t);
            m_i[i] = t;
            rsum[i] = 0.0f;
#pragma unroll
            for (int j = 0; j < 4; j++) {
                p[i][j] = __expf(s[i][j] - t);
                rsum[i] += p[i][j];
            }
        }
        __syncthreads();   // red(max) reads done; KPs(S) reads done

        // Write partial row sums and P^T (into the K buffer)
#pragma unroll
        for (int i = 0; i < 4; i++) {
            red[((ty << 2) + i) * 17 + tx] = rsum[i];
#pragma unroll
            for (int j = 0; j < 4; j++)
                KPs[((tx << 2) + j) * SMP + (ty << 2) + i] = p[i][j];
        }
        __syncthreads();

        // Rescale accumulators, fold in row sums
#pragma unroll
        for (int i = 0; i < 4; i++) {
            int r = (ty << 2) + i;
            float t = 0.0f;
#pragma unroll
            for (int k2 = 0; k2 < 16; k2++) t += red[r * 17 + k2];
            l_i[i] = l_i[i] * alpha[i] + t;
#pragma unroll
            for (int j = 0; j < 4; j++) o[i][j] *= alpha[i];
        }

        // O += P V   (P^T stored in KPs[c][r], V in Vs[c][j])
#pragma unroll 16
        for (int c = 0; c < 64; c++) {
            float4 pa = *(const float4*)&KPs[c * SMP + (ty << 2)];
            float4 vb = *(const float4*)&Vs[c * SMP + (tx << 2)];
            o[0][0] += pa.x * vb.x; o[0][1] += pa.x * vb.y; o[0][2] += pa.x * vb.z; o[0][3] += pa.x * vb.w;
            o[1][0] += pa.y * vb.x; o[1][1] += pa.y * vb.y; o[1][2] += pa.y * vb.z; o[1][3] += pa.y * vb.w;
            o[2][0] += pa.z * vb.x; o[2][1] += pa.z * vb.y; o[2][2] += pa.z * vb.z; o[2][3] += pa.z * vb.w;
            o[3][0] += pa.w * vb.x; o[3][1] += pa.w * vb.y; o[3][2] += pa.w * vb.z; o[3][3] += pa.w * vb.w;
        }
    }

    // Normalize + write out
#pragma unroll
    for (int i = 0; i < 4; i++) {
        float inv = 1.0f / l_i[i];
        float4 v = make_float4(o[i][0] * inv, o[i][1] * inv, o[i][2] * inv, o[i][3] * inv);
        int r = q0 + (ty << 2) + i;
        *(float4*)&O[(b * SEQ + r) * DMODEL + h * HDIM + (tx << 2)] = v;
    }
}

// ---------------------------------------------------------------------------
// Launch
// ---------------------------------------------------------------------------
extern "C" void kernel_launch(void* const* d_in, const int* in_sizes, int n_in,
                              void* d_out, int out_size)
{
    const float* x  = (const float*)d_in[0];
    const float* Wq = (const float*)d_in[1];
    const float* Wk = (const float*)d_in[2];
    const float* Wv = (const float*)d_in[3];
    const float* Wo = (const float*)d_in[4];
    float* out = (float*)d_out;

    float* scratch = nullptr;
    cudaGetSymbolAddress((void**)&scratch, g_scratch);
    const size_t PLANE = (size_t)MTOT * DMODEL;   // 8388608
    float* Qb = scratch;
    float* Kb = scratch + PLANE;
    float* Vb = scratch + 2 * PLANE;
    float* Ab = scratch + 3 * PLANE;

    dim3 ggrid(DMODEL / 128, MTOT / 128);   // (8, 64)
    gemm_nt_tf32_kernel<<<ggrid, 256>>>(x, Wq, Qb, MTOT, DMODEL, DMODEL);
    gemm_nt_tf32_kernel<<<ggrid, 256>>>(x, Wk, Kb, MTOT, DMODEL, DMODEL);
    gemm_nt_tf32_kernel<<<ggrid, 256>>>(x, Wv, Vb, MTOT, DMODEL, DMODEL);

    int smem_bytes = (3 * 64 * SMP + 64 * 17) * (int)sizeof(float);  // 56576
    cudaFuncSetAttribute(flash_kernel, cudaFuncAttributeMaxDynamicSharedMemorySize, smem_bytes);
    flash_kernel<<<dim3(SEQ / 64, BATCH * NHEADS), 256, smem_bytes>>>(Qb, Kb, Vb, Ab);

    gemm_nt_tf32_kernel<<<ggrid, 256>>>(Ab, Wo, out, MTOT, DMODEL, DMODEL);
}

// round 5
// speedup vs baseline: 1.4218x; 1.3467x over previous
#include <cuda_runtime.h>
#include <cstdint>

// ---------------------------------------------------------------------------
// MultiHeadSelfAttention: B=4, S=2048, D=1024, H=16, Dh=64, fp32, causal.
//
// Stage 1: Q,K,V projections — bf16 hi/lo 3x-split NT GEMM (mma m16n8k16)
// Stage 2: flash attention, fp32 FFMA, 128x128 tiles, 8x8 per-thread
// Stage 3: out = A @ Wo^T — same bf16 GEMM
// ---------------------------------------------------------------------------

#define SEQ 2048
#define BATCH 4
#define DMODEL 1024
#define NHEADS 16
#define HDIM 64
#define MTOT (BATCH * SEQ)          // 8192

__device__ float g_scratch[4ull * MTOT * DMODEL];

// ---------------------------------------------------------------------------
// bf16 split helpers
// ---------------------------------------------------------------------------
__device__ __forceinline__ void split2(float x0, float x1, uint32_t& h, uint32_t& l) {
    uint32_t hh;
    asm("cvt.rn.bf16x2.f32 %0, %1, %2;" : "=r"(hh) : "f"(x1), "f"(x0));  // hi-half=x1, lo-half=x0
    float f0 = __uint_as_float(hh << 16);
    float f1 = __uint_as_float(hh & 0xFFFF0000u);
    float r0 = x0 - f0;
    float r1 = x1 - f1;
    uint32_t ll;
    asm("cvt.rn.bf16x2.f32 %0, %1, %2;" : "=r"(ll) : "f"(r1), "f"(r0));
    h = hh; l = ll;
}

__device__ __forceinline__ void mma_bf16(float* d, const uint32_t* a, const uint32_t* b) {
    asm volatile(
        "mma.sync.aligned.m16n8k16.row.col.f32.bf16.bf16.f32 "
        "{%0,%1,%2,%3}, {%4,%5,%6,%7}, {%8,%9}, {%0,%1,%2,%3};"
        : "+f"(d[0]), "+f"(d[1]), "+f"(d[2]), "+f"(d[3])
        : "r"(a[0]), "r"(a[1]), "r"(a[2]), "r"(a[3]), "r"(b[0]), "r"(b[1]));
}

// ---------------------------------------------------------------------------
// NT GEMM via bf16 3x split: C[m,n] = sum_k A[m*K+k] * B[n*K+k]
// 128x128 tile, k-slab 16, double-buffered packed-bf16x2 smem planes.
// 256 threads = 8 warps (2m x 4n), warp tile 64x32, mma m16n8k16.
// Row stride 12 u32 (8 k-pairs + 4 pad) -> conflict-free fragment LDS.
// ---------------------------------------------------------------------------
#define SST2 12

__global__ __launch_bounds__(256, 1) void gemm_nt_bf16_kernel(
    const float* __restrict__ A, const float* __restrict__ B, float* __restrict__ C,
    int M, int N, int K)
{
    __shared__ uint32_t smAh[2][128 * SST2];
    __shared__ uint32_t smAl[2][128 * SST2];
    __shared__ uint32_t smBh[2][128 * SST2];
    __shared__ uint32_t smBl[2][128 * SST2];

    const int bm = blockIdx.y * 128;
    const int bn = blockIdx.x * 128;
    const int tid = threadIdx.x;
    const int warp = tid >> 5;
    const int lane = tid & 31;
    const int g = lane >> 2;
    const int t = lane & 3;
    const int wm = (warp & 1) * 64;
    const int wn = (warp >> 1) * 32;

    const int lr = tid >> 2;          // 0..63
    const int lc = (tid & 3) << 2;    // 0,4,8,12
    const int pi = lc >> 1;           // pair index 0,2,4,6

    const float* Aptr0 = A + (size_t)(bm + lr) * K + lc;
    const float* Aptr1 = A + (size_t)(bm + lr + 64) * K + lc;
    const float* Bptr0 = B + (size_t)(bn + lr) * K + lc;
    const float* Bptr1 = B + (size_t)(bn + lr + 64) * K + lc;

    // split+store one float4 into hi/lo planes
    auto split_store = [&](uint32_t* Ph, uint32_t* Pl, int idx, float4 v) {
        uint32_t h01, l01, h23, l23;
        split2(v.x, v.y, h01, l01);
        split2(v.z, v.w, h23, l23);
        Ph[idx] = h01; Ph[idx + 1] = h23;
        Pl[idx] = l01; Pl[idx + 1] = l23;
    };

    // preload slab 0
    split_store(smAh[0], smAl[0], lr * SST2 + pi,        *(const float4*)Aptr0);
    split_store(smAh[0], smAl[0], (lr + 64) * SST2 + pi, *(const float4*)Aptr1);
    split_store(smBh[0], smBl[0], lr * SST2 + pi,        *(const float4*)Bptr0);
    split_store(smBh[0], smBl[0], (lr + 64) * SST2 + pi, *(const float4*)Bptr1);
    __syncthreads();

    float acc[4][4][4];
#pragma unroll
    for (int mt = 0; mt < 4; mt++)
#pragma unroll
        for (int nt = 0; nt < 4; nt++)
#pragma unroll
            for (int r = 0; r < 4; r++) acc[mt][nt][r] = 0.0f;

    int buf = 0;
    for (int k0 = 16; k0 <= K; k0 += 16) {
        const bool more = (k0 < K);
        float4 na0, na1, nb0, nb1;
        if (more) {
            na0 = *(const float4*)(Aptr0 + k0);
            na1 = *(const float4*)(Aptr1 + k0);
            nb0 = *(const float4*)(Bptr0 + k0);
            nb1 = *(const float4*)(Bptr1 + k0);
        }

        const uint32_t* Ahb = smAh[buf];
        const uint32_t* Alb = smAl[buf];
        const uint32_t* Bhb = smBh[buf];
        const uint32_t* Blb = smBl[buf];

        uint32_t ah[4][4], al[4][4];
#pragma unroll
        for (int mt = 0; mt < 4; mt++) {
            int m0 = wm + mt * 16 + g;
            ah[mt][0] = Ahb[m0 * SST2 + t];
            ah[mt][1] = Ahb[(m0 + 8) * SST2 + t];
            ah[mt][2] = Ahb[m0 * SST2 + t + 4];
            ah[mt][3] = Ahb[(m0 + 8) * SST2 + t + 4];
            al[mt][0] = Alb[m0 * SST2 + t];
            al[mt][1] = Alb[(m0 + 8) * SST2 + t];
            al[mt][2] = Alb[m0 * SST2 + t + 4];
            al[mt][3] = Alb[(m0 + 8) * SST2 + t + 4];
        }
        uint32_t bh[4][2], bl[4][2];
#pragma unroll
        for (int nt = 0; nt < 4; nt++) {
            int n0 = wn + nt * 8 + g;
            bh[nt][0] = Bhb[n0 * SST2 + t];
            bh[nt][1] = Bhb[n0 * SST2 + t + 4];
            bl[nt][0] = Blb[n0 * SST2 + t];
            bl[nt][1] = Blb[n0 * SST2 + t + 4];
        }
#pragma unroll
        for (int mt = 0; mt < 4; mt++)
#pragma unroll
            for (int nt = 0; nt < 4; nt++) {
                mma_bf16(acc[mt][nt], ah[mt], bh[nt]);
                mma_bf16(acc[mt][nt], ah[mt], bl[nt]);
                mma_bf16(acc[mt][nt], al[mt], bh[nt]);
            }

        if (more) {
            int nbuf = buf ^ 1;
            split_store(smAh[nbuf], smAl[nbuf], lr * SST2 + pi,        na0);
            split_store(smAh[nbuf], smAl[nbuf], (lr + 64) * SST2 + pi, na1);
            split_store(smBh[nbuf], smBl[nbuf], lr * SST2 + pi,        nb0);
            split_store(smBh[nbuf], smBl[nbuf], (lr + 64) * SST2 + pi, nb1);
            __syncthreads();
            buf = nbuf;
        }
    }

    // epilogue: d0:(g,2t) d1:(g,2t+1) d2:(g+8,2t) d3:(g+8,2t+1)
#pragma unroll
    for (int mt = 0; mt < 4; mt++) {
#pragma unroll
        for (int nt = 0; nt < 4; nt++) {
            int m0 = bm + wm + mt * 16 + g;
            int n0 = bn + wn + nt * 8 + 2 * t;
            *(float2*)&C[(size_t)m0 * N + n0]       = make_float2(acc[mt][nt][0], acc[mt][nt][1]);
            *(float2*)&C[(size_t)(m0 + 8) * N + n0] = make_float2(acc[mt][nt][2], acc[mt][nt][3]);
        }
    }
}

// ---------------------------------------------------------------------------
// Flash attention, fp32, causal. 128x128 tiles, 8x8 per-thread S-tile.
// grid: (SEQ/128, BATCH*NHEADS) = (16, 64). 256 threads.
// Row mapping per thread: rows {4ty+i, 64+4ty+i}, cols {4tx+j, 64+4tx+j}.
// Softmax row state (m, l, alpha) lives in smem.
// ---------------------------------------------------------------------------
#define QSTR 132   // Qs/Ks row stride (128 + 4)
#define VSTR 68    // Vs row stride (64 + 4)
#define PSTR 132   // Ps row stride

__global__ __launch_bounds__(256, 1) void flash_kernel(
    const float* __restrict__ Q, const float* __restrict__ K,
    const float* __restrict__ V, float* __restrict__ O)
{
    extern __shared__ float sm[];
    float* Qs = sm;                        // [64][132]  Q^T: [d][r]
    float* Ks = Qs + 64 * QSTR;            // [64][132]  K^T: [d][c]
    float* Vs = Ks + 64 * QSTR;            // [128][68]  V:   [c][dv]
    float* Ps = Vs + 128 * VSTR;           // [128][132] P:   [r][c]
    float* red = Ps + 128 * PSTR;          // [128][17]
    float* mstate = red + 128 * 17;        // [128]
    float* lstate = mstate + 128;          // [128]
    float* astate = lstate + 128;          // [128]

    const int tid = threadIdx.x;
    const int tx = tid & 15;
    const int ty = tid >> 4;
    const int qt = (gridDim.x - 1) - blockIdx.x;   // heavy tiles first
    const int q0 = qt * 128;
    const int bh = blockIdx.y;
    const int b = bh >> 4, h = bh & 15;

    const size_t base = (size_t)(b * SEQ) * DMODEL + h * HDIM;
    const float* Qp = Q + base;
    const float* Kp = K + base;
    const float* Vp = V + base;

    // Load Q tile transposed: Qs[d][r], 128 rows x 64 d
#pragma unroll
    for (int i = 0; i < 32; i++) {
        int idx = tid + i * 256;    // 0..8191
        int d = idx & 63;
        int r = idx >> 6;
        Qs[d * QSTR + r] = Qp[(size_t)(q0 + r) * DMODEL + d];
    }
    if (tid < 128) { mstate[tid] = -1e30f; lstate[tid] = 0.0f; }

    float o[8][4];
#pragma unroll
    for (int i = 0; i < 8; i++)
#pragma unroll
        for (int j = 0; j < 4; j++) o[i][j] = 0.0f;

    const float scale = 0.125f;   // 1/sqrt(64)

    for (int kt = 0; kt <= qt; kt++) {
        const int k0 = kt * 128;
        __syncthreads();   // S1: prev iter's Ps/Vs reads and Ks reads done

        // Load K^T and V
#pragma unroll
        for (int i = 0; i < 32; i++) {
            int idx = tid + i * 256;
            int d = idx & 63;
            int c = idx >> 6;
            float kv = Kp[(size_t)(k0 + c) * DMODEL + d];
            float vv = Vp[(size_t)(k0 + c) * DMODEL + d];
            Ks[d * QSTR + c] = kv;
            Vs[c * VSTR + d] = vv;
        }
        __syncthreads();   // S2

        // S = Q K^T : 8x8 per thread
        float s[8][8];
#pragma unroll
        for (int i = 0; i < 8; i++)
#pragma unroll
            for (int j = 0; j < 8; j++) s[i][j] = 0.0f;

#pragma unroll 4
        for (int d = 0; d < 64; d++) {
            float4 qa = *(const float4*)&Qs[d * QSTR + 4 * ty];
            float4 qb = *(const float4*)&Qs[d * QSTR + 4 * ty + 64];
            float4 ka = *(const float4*)&Ks[d * QSTR + 4 * tx];
            float4 kb = *(const float4*)&Ks[d * QSTR + 4 * tx + 64];
            float qv[8] = {qa.x, qa.y, qa.z, qa.w, qb.x, qb.y, qb.z, qb.w};
            float kv[8] = {ka.x, ka.y, ka.z, ka.w, kb.x, kb.y, kb.z, kb.w};
#pragma unroll
            for (int i = 0; i < 8; i++)
#pragma unroll
                for (int j = 0; j < 8; j++) s[i][j] += qv[i] * kv[j];
        }

        // scale + causal mask
        if (kt == qt) {
#pragma unroll
            for (int i = 0; i < 8; i++) {
                int R = q0 + 4 * ty + (i & 3) + 64 * (i >> 2);
#pragma unroll
                for (int j = 0; j < 8; j++) {
                    int Cc = k0 + 4 * tx + (j & 3) + 64 * (j >> 2);
                    s[i][j] = (Cc <= R) ? s[i][j] * scale : -1e30f;
                }
            }
        } else {
#pragma unroll
            for (int i = 0; i < 8; i++)
#pragma unroll
                for (int j = 0; j < 8; j++) s[i][j] *= scale;
        }

        // row-max partials
#pragma unroll
        for (int i = 0; i < 8; i++) {
            int rl = 4 * ty + (i & 3) + 64 * (i >> 2);
            float rm = s[i][0];
#pragma unroll
            for (int j = 1; j < 8; j++) rm = fmaxf(rm, s[i][j]);
            red[rl * 17 + tx] = rm;
        }
        __syncthreads();   // S3

        if (tid < 128) {
            float mo = mstate[tid];
            float mx = mo;
#pragma unroll
            for (int k2 = 0; k2 < 16; k2++) mx = fmaxf(mx, red[tid * 17 + k2]);
            mstate[tid] = mx;
            astate[tid] = __expf(mo - mx);
        }
        __syncthreads();   // S4

        // p = exp(s - m), store P row-major, row-sum partials, rescale o
#pragma unroll
        for (int i = 0; i < 8; i++) {
            int rl = 4 * ty + (i & 3) + 64 * (i >> 2);
            float mrow = mstate[rl];
            float rowsum = 0.0f;
#pragma unroll
            for (int j = 0; j < 8; j++) {
                s[i][j] = __expf(s[i][j] - mrow);
                rowsum += s[i][j];
            }
            *(float4*)&Ps[rl * PSTR + 4 * tx]      = make_float4(s[i][0], s[i][1], s[i][2], s[i][3]);
            *(float4*)&Ps[rl * PSTR + 4 * tx + 64] = make_float4(s[i][4], s[i][5], s[i][6], s[i][7]);
            red[rl * 17 + tx] = rowsum;
            float a = astate[rl];
#pragma unroll
            for (int jj = 0; jj < 4; jj++) o[i][jj] *= a;
        }
        __syncthreads();   // S5

        if (tid < 128) {
            float tsum = 0.0f;
#pragma unroll
            for (int k2 = 0; k2 < 16; k2++) tsum += red[tid * 17 + k2];
            lstate[tid] = lstate[tid] * astate[tid] + tsum;
        }

        // O += P V
#pragma unroll 2
        for (int c = 0; c < 128; c++) {
            float4 v4 = *(const float4*)&Vs[c * VSTR + 4 * tx];
            float pv[8];
#pragma unroll
            for (int i = 0; i < 8; i++) {
                int rl = 4 * ty + (i & 3) + 64 * (i >> 2);
                pv[i] = Ps[rl * PSTR + c];
            }
#pragma unroll
            for (int i = 0; i < 8; i++) {
                o[i][0] += pv[i] * v4.x;
                o[i][1] += pv[i] * v4.y;
                o[i][2] += pv[i] * v4.z;
                o[i][3] += pv[i] * v4.w;
            }
        }
    }

    __syncthreads();   // lstate final

    // normalize + write out: row q0+rl, col h*64 + 4*tx
#pragma unroll
    for (int i = 0; i < 8; i++) {
        int rl = 4 * ty + (i & 3) + 64 * (i >> 2);
        float inv = 1.0f / lstate[rl];
        float4 v = make_float4(o[i][0] * inv, o[i][1] * inv, o[i][2] * inv, o[i][3] * inv);
        *(float4*)&O[(size_t)(b * SEQ + q0 + rl) * DMODEL + h * HDIM + 4 * tx] = v;
    }
}

// ---------------------------------------------------------------------------
// Launch
// ---------------------------------------------------------------------------
extern "C" void kernel_launch(void* const* d_in, const int* in_sizes, int n_in,
                              void* d_out, int out_size)
{
    const float* x  = (const float*)d_in[0];
    const float* Wq = (const float*)d_in[1];
    const float* Wk = (const float*)d_in[2];
    const float* Wv = (const float*)d_in[3];
    const float* Wo = (const float*)d_in[4];
    float* out = (float*)d_out;

    float* scratch = nullptr;
    cudaGetSymbolAddress((void**)&scratch, g_scratch);
    const size_t PLANE = (size_t)MTOT * DMODEL;
    float* Qb = scratch;
    float* Kb = scratch + PLANE;
    float* Vb = scratch + 2 * PLANE;
    float* Ab = scratch + 3 * PLANE;

    dim3 ggrid(DMODEL / 128, MTOT / 128);   // (8, 64)
    gemm_nt_bf16_kernel<<<ggrid, 256>>>(x, Wq, Qb, MTOT, DMODEL, DMODEL);
    gemm_nt_bf16_kernel<<<ggrid, 256>>>(x, Wk, Kb, MTOT, DMODEL, DMODEL);
    gemm_nt_bf16_kernel<<<ggrid, 256>>>(x, Wv, Vb, MTOT, DMODEL, DMODEL);

    int smem_bytes = (2 * 64 * QSTR + 128 * VSTR + 128 * PSTR + 128 * 17 + 3 * 128) * (int)sizeof(float);  // 180224
    cudaFuncSetAttribute(flash_kernel, cudaFuncAttributeMaxDynamicSharedMemorySize, smem_bytes);
    flash_kernel<<<dim3(SEQ / 128, BATCH * NHEADS), 256, smem_bytes>>>(Qb, Kb, Vb, Ab);

    gemm_nt_bf16_kernel<<<ggrid, 256>>>(Ab, Wo, out, MTOT, DMODEL, DMODEL);
}

// round 7
// speedup vs baseline: 2.2602x; 1.5897x over previous
#include <cuda_runtime.h>
#include <cstdint>

// ---------------------------------------------------------------------------
// MultiHeadSelfAttention: B=4, S=2048, D=1024, H=16, Dh=64, fp32, causal.
//
// Stage 1: Q,K,V projections — bf16 hi/lo 3x-split NT GEMM (mma m16n8k16)
// Stage 2: flash attention — bf16 hi/lo 3x-split tensor-core, P kept in regs
// Stage 3: out = A @ Wo^T — same bf16 GEMM
// ---------------------------------------------------------------------------

#define SEQ 2048
#define BATCH 4
#define DMODEL 1024
#define NHEADS 16
#define HDIM 64
#define MTOT (BATCH * SEQ)          // 8192

__device__ float g_scratch[4ull * MTOT * DMODEL];

// ---------------------------------------------------------------------------
// bf16 split helpers
// ---------------------------------------------------------------------------
__device__ __forceinline__ void split2(float x0, float x1, uint32_t& h, uint32_t& l) {
    uint32_t hh;
    asm("cvt.rn.bf16x2.f32 %0, %1, %2;" : "=r"(hh) : "f"(x1), "f"(x0));  // hi=x1, lo=x0
    float f0 = __uint_as_float(hh << 16);
    float f1 = __uint_as_float(hh & 0xFFFF0000u);
    float r0 = x0 - f0;
    float r1 = x1 - f1;
    uint32_t ll;
    asm("cvt.rn.bf16x2.f32 %0, %1, %2;" : "=r"(ll) : "f"(r1), "f"(r0));
    h = hh; l = ll;
}

__device__ __forceinline__ void mma_bf16(float* d, const uint32_t* a, const uint32_t* b) {
    asm volatile(
        "mma.sync.aligned.m16n8k16.row.col.f32.bf16.bf16.f32 "
        "{%0,%1,%2,%3}, {%4,%5,%6,%7}, {%8,%9}, {%0,%1,%2,%3};"
        : "+f"(d[0]), "+f"(d[1]), "+f"(d[2]), "+f"(d[3])
        : "r"(a[0]), "r"(a[1]), "r"(a[2]), "r"(a[3]), "r"(b[0]), "r"(b[1]));
}

// ---------------------------------------------------------------------------
// NT GEMM via bf16 3x split (unchanged from R5, measured ~247 TF/s raw)
// ---------------------------------------------------------------------------
#define SST2 12

__global__ __launch_bounds__(256, 1) void gemm_nt_bf16_kernel(
    const float* __restrict__ A, const float* __restrict__ B, float* __restrict__ C,
    int M, int N, int K)
{
    __shared__ uint32_t smAh[2][128 * SST2];
    __shared__ uint32_t smAl[2][128 * SST2];
    __shared__ uint32_t smBh[2][128 * SST2];
    __shared__ uint32_t smBl[2][128 * SST2];

    const int bm = blockIdx.y * 128;
    const int bn = blockIdx.x * 128;
    const int tid = threadIdx.x;
    const int warp = tid >> 5;
    const int lane = tid & 31;
    const int g = lane >> 2;
    const int t = lane & 3;
    const int wm = (warp & 1) * 64;
    const int wn = (warp >> 1) * 32;

    const int lr = tid >> 2;
    const int lc = (tid & 3) << 2;
    const int pi = lc >> 1;

    const float* Aptr0 = A + (size_t)(bm + lr) * K + lc;
    const float* Aptr1 = A + (size_t)(bm + lr + 64) * K + lc;
    const float* Bptr0 = B + (size_t)(bn + lr) * K + lc;
    const float* Bptr1 = B + (size_t)(bn + lr + 64) * K + lc;

    auto split_store = [&](uint32_t* Ph, uint32_t* Pl, int idx, float4 v) {
        uint32_t h01, l01, h23, l23;
        split2(v.x, v.y, h01, l01);
        split2(v.z, v.w, h23, l23);
        Ph[idx] = h01; Ph[idx + 1] = h23;
        Pl[idx] = l01; Pl[idx + 1] = l23;
    };

    split_store(smAh[0], smAl[0], lr * SST2 + pi,        *(const float4*)Aptr0);
    split_store(smAh[0], smAl[0], (lr + 64) * SST2 + pi, *(const float4*)Aptr1);
    split_store(smBh[0], smBl[0], lr * SST2 + pi,        *(const float4*)Bptr0);
    split_store(smBh[0], smBl[0], (lr + 64) * SST2 + pi, *(const float4*)Bptr1);
    __syncthreads();

    float acc[4][4][4];
#pragma unroll
    for (int mt = 0; mt < 4; mt++)
#pragma unroll
        for (int nt = 0; nt < 4; nt++)
#pragma unroll
            for (int r = 0; r < 4; r++) acc[mt][nt][r] = 0.0f;

    int buf = 0;
    for (int k0 = 16; k0 <= K; k0 += 16) {
        const bool more = (k0 < K);
        float4 na0, na1, nb0, nb1;
        if (more) {
            na0 = *(const float4*)(Aptr0 + k0);
            na1 = *(const float4*)(Aptr1 + k0);
            nb0 = *(const float4*)(Bptr0 + k0);
            nb1 = *(const float4*)(Bptr1 + k0);
        }

        const uint32_t* Ahb = smAh[buf];
        const uint32_t* Alb = smAl[buf];
        const uint32_t* Bhb = smBh[buf];
        const uint32_t* Blb = smBl[buf];

        uint32_t ah[4][4], al[4][4];
#pragma unroll
        for (int mt = 0; mt < 4; mt++) {
            int m0 = wm + mt * 16 + g;
            ah[mt][0] = Ahb[m0 * SST2 + t];
            ah[mt][1] = Ahb[(m0 + 8) * SST2 + t];
            ah[mt][2] = Ahb[m0 * SST2 + t + 4];
            ah[mt][3] = Ahb[(m0 + 8) * SST2 + t + 4];
            al[mt][0] = Alb[m0 * SST2 + t];
            al[mt][1] = Alb[(m0 + 8) * SST2 + t];
            al[mt][2] = Alb[m0 * SST2 + t + 4];
            al[mt][3] = Alb[(m0 + 8) * SST2 + t + 4];
        }
        uint32_t bh[4][2], bl[4][2];
#pragma unroll
        for (int nt = 0; nt < 4; nt++) {
            int n0 = wn + nt * 8 + g;
            bh[nt][0] = Bhb[n0 * SST2 + t];
            bh[nt][1] = Bhb[n0 * SST2 + t + 4];
            bl[nt][0] = Blb[n0 * SST2 + t];
            bl[nt][1] = Blb[n0 * SST2 + t + 4];
        }
#pragma unroll
        for (int mt = 0; mt < 4; mt++)
#pragma unroll
            for (int nt = 0; nt < 4; nt++) {
                mma_bf16(acc[mt][nt], ah[mt], bh[nt]);
                mma_bf16(acc[mt][nt], ah[mt], bl[nt]);
                mma_bf16(acc[mt][nt], al[mt], bh[nt]);
            }

        if (more) {
            int nbuf = buf ^ 1;
            split_store(smAh[nbuf], smAl[nbuf], lr * SST2 + pi,        na0);
            split_store(smAh[nbuf], smAl[nbuf], (lr + 64) * SST2 + pi, na1);
            split_store(smBh[nbuf], smBl[nbuf], lr * SST2 + pi,        nb0);
            split_store(smBh[nbuf], smBl[nbuf], (lr + 64) * SST2 + pi, nb1);
            __syncthreads();
            buf = nbuf;
        }
    }

#pragma unroll
    for (int mt = 0; mt < 4; mt++) {
#pragma unroll
        for (int nt = 0; nt < 4; nt++) {
            int m0 = bm + wm + mt * 16 + g;
            int n0 = bn + wn + nt * 8 + 2 * t;
            *(float2*)&C[(size_t)m0 * N + n0]       = make_float2(acc[mt][nt][0], acc[mt][nt][1]);
            *(float2*)&C[(size_t)(m0 + 8) * N + n0] = make_float2(acc[mt][nt][2], acc[mt][nt][3]);
        }
    }
}

// ---------------------------------------------------------------------------
// Tensor-core flash attention, bf16 3x split, causal.
// grid: (SEQ/128, BATCH*NHEADS) = (16, 64). 256 threads = 8 warps.
// Each warp owns 16 query rows. Q-tile 128 x 64, K-tile 128 x 64, V 128 x 64.
// Q/K smem: bf16x2 pairs over d, [row][36]. V smem: pairs over c, [c2][68].
// S/P stay in registers; P A-fragments are repacked S d-registers.
// ---------------------------------------------------------------------------
#define FQS 36    // Q/K row stride in u32
#define FVS 68    // V row stride in u32

__global__ __launch_bounds__(256, 1) void flash_tc_kernel(
    const float* __restrict__ Q, const float* __restrict__ K,
    const float* __restrict__ V, float* __restrict__ O)
{
    extern __shared__ uint32_t smu[];
    uint32_t* Qh = smu;                 // 128*36
    uint32_t* Ql = Qh + 128 * FQS;
    uint32_t* Kh = Ql + 128 * FQS;      // [c][d2]
    uint32_t* Kl = Kh + 128 * FQS;
    uint32_t* Vh = Kl + 128 * FQS;      // [c2][dv], 64*68
    uint32_t* Vl = Vh + 64 * FVS;

    const int tid = threadIdx.x;
    const int warp = tid >> 5;
    const int lane = tid & 31;
    const int g = lane >> 2;
    const int t = lane & 3;

    const int qt = (gridDim.x - 1) - blockIdx.x;   // heavy tiles first
    const int q0 = qt * 128;
    const int bh_ = blockIdx.y;
    const int b = bh_ >> 4, h = bh_ & 15;

    const size_t base = (size_t)(b * SEQ) * DMODEL + h * HDIM;
    const float* Qp = Q + base;
    const float* Kp = K + base;
    const float* Vp = V + base;

    // ---- load + convert Q tile (scale folded in) ----
#pragma unroll
    for (int i = 0; i < 8; i++) {
        int idx = tid + i * 256;        // 0..2047
        int dq = idx & 15;
        int r = idx >> 4;
        float4 v = *(const float4*)&Qp[(size_t)(q0 + r) * DMODEL + dq * 4];
        v.x *= 0.125f; v.y *= 0.125f; v.z *= 0.125f; v.w *= 0.125f;
        uint32_t h0, l0, h1, l1;
        split2(v.x, v.y, h0, l0);
        split2(v.z, v.w, h1, l1);
        Qh[r * FQS + dq * 2] = h0; Qh[r * FQS + dq * 2 + 1] = h1;
        Ql[r * FQS + dq * 2] = l0; Ql[r * FQS + dq * 2 + 1] = l1;
    }
    __syncthreads();

    // ---- per-warp Q fragments (held in regs for whole kernel) ----
    uint32_t qfh[4][4], qfl[4][4];
    const int qrow = warp * 16 + g;
#pragma unroll
    for (int kc = 0; kc < 4; kc++) {
        qfh[kc][0] = Qh[qrow * FQS + 8 * kc + t];
        qfh[kc][1] = Qh[(qrow + 8) * FQS + 8 * kc + t];
        qfh[kc][2] = Qh[qrow * FQS + 8 * kc + t + 4];
        qfh[kc][3] = Qh[(qrow + 8) * FQS + 8 * kc + t + 4];
        qfl[kc][0] = Ql[qrow * FQS + 8 * kc + t];
        qfl[kc][1] = Ql[(qrow + 8) * FQS + 8 * kc + t];
        qfl[kc][2] = Ql[qrow * FQS + 8 * kc + t + 4];
        qfl[kc][3] = Ql[(qrow + 8) * FQS + 8 * kc + t + 4];
    }

    float m0 = -1e30f, m1 = -1e30f, l0 = 0.0f, l1 = 0.0f;
    float o[8][4];
#pragma unroll
    for (int dt = 0; dt < 8; dt++)
#pragma unroll
        for (int r = 0; r < 4; r++) o[dt][r] = 0.0f;

    const int R0g = q0 + warp * 16 + g;       // global row of regs 0,1
    const int R1g = R0g + 8;                  // global row of regs 2,3

    for (int kt = 0; kt <= qt; kt++) {
        const int k0 = kt * 128;
        __syncthreads();   // prior iter's fragment reads done

        // ---- load + convert K tile: Kh/Kl[c][d2] ----
#pragma unroll
        for (int i = 0; i < 8; i++) {
            int idx = tid + i * 256;
            int dq = idx & 15;
            int c = idx >> 4;
            float4 v = *(const float4*)&Kp[(size_t)(k0 + c) * DMODEL + dq * 4];
            uint32_t h0, l0_, h1, l1_;
            split2(v.x, v.y, h0, l0_);
            split2(v.z, v.w, h1, l1_);
            Kh[c * FQS + dq * 2] = h0; Kh[c * FQS + dq * 2 + 1] = h1;
            Kl[c * FQS + dq * 2] = l0_; Kl[c * FQS + dq * 2 + 1] = l1_;
        }
        // ---- load + convert V tile: Vh/Vl[c2][dv] (pairs over c) ----
#pragma unroll
        for (int i = 0; i < 16; i++) {
            int idx = tid + i * 256;    // 0..4095
            int dv = idx & 63;
            int c2 = idx >> 6;          // 0..63
            float v0 = Vp[(size_t)(k0 + 2 * c2) * DMODEL + dv];
            float v1 = Vp[(size_t)(k0 + 2 * c2 + 1) * DMODEL + dv];
            uint32_t hh, ll;
            split2(v0, v1, hh, ll);
            Vh[c2 * FVS + dv] = hh;
            Vl[c2 * FVS + dv] = ll;
        }
        __syncthreads();

        // ---- S = (Q*scale) K^T : 16 n-tiles x 4 regs, fp32 ----
        float s[16][4];
#pragma unroll
        for (int nt = 0; nt < 16; nt++)
#pragma unroll
            for (int r = 0; r < 4; r++) s[nt][r] = 0.0f;

#pragma unroll
        for (int kc = 0; kc < 4; kc++) {
#pragma unroll
            for (int nt = 0; nt < 16; nt++) {
                const int kr = (nt * 8 + g) * FQS + 8 * kc + t;
                uint32_t bh[2] = { Kh[kr], Kh[kr + 4] };
                uint32_t bl[2] = { Kl[kr], Kl[kr + 4] };
                mma_bf16(s[nt], qfh[kc], bh);
                mma_bf16(s[nt], qfh[kc], bl);
                mma_bf16(s[nt], qfl[kc], bh);
            }
        }

        // ---- causal mask on diagonal tile ----
        if (kt == qt) {
#pragma unroll
            for (int nt = 0; nt < 16; nt++) {
                int C0 = k0 + nt * 8 + 2 * t;
                int C1 = C0 + 1;
                if (C0 > R0g) s[nt][0] = -1e30f;
                if (C1 > R0g) s[nt][1] = -1e30f;
                if (C0 > R1g) s[nt][2] = -1e30f;
                if (C1 > R1g) s[nt][3] = -1e30f;
            }
        }

        // ---- online softmax (rows g, g+8; quad reduce over t) ----
        float tm0 = -1e30f, tm1 = -1e30f;
#pragma unroll
        for (int nt = 0; nt < 16; nt++) {
            tm0 = fmaxf(tm0, fmaxf(s[nt][0], s[nt][1]));
            tm1 = fmaxf(tm1, fmaxf(s[nt][2], s[nt][3]));
        }
        tm0 = fmaxf(tm0, __shfl_xor_sync(0xffffffffu, tm0, 1));
        tm0 = fmaxf(tm0, __shfl_xor_sync(0xffffffffu, tm0, 2));
        tm1 = fmaxf(tm1, __shfl_xor_sync(0xffffffffu, tm1, 1));
        tm1 = fmaxf(tm1, __shfl_xor_sync(0xffffffffu, tm1, 2));

        float mn0 = fmaxf(m0, tm0), mn1 = fmaxf(m1, tm1);
        float a0 = __expf(m0 - mn0), a1 = __expf(m1 - mn1);
        m0 = mn0; m1 = mn1;

        float rs0 = 0.0f, rs1 = 0.0f;
#pragma unroll
        for (int nt = 0; nt < 16; nt++) {
            s[nt][0] = __expf(s[nt][0] - mn0);
            s[nt][1] = __expf(s[nt][1] - mn0);
            s[nt][2] = __expf(s[nt][2] - mn1);
            s[nt][3] = __expf(s[nt][3] - mn1);
            rs0 += s[nt][0] + s[nt][1];
            rs1 += s[nt][2] + s[nt][3];
        }
        rs0 += __shfl_xor_sync(0xffffffffu, rs0, 1);
        rs0 += __shfl_xor_sync(0xffffffffu, rs0, 2);
        rs1 += __shfl_xor_sync(0xffffffffu, rs1, 1);
        rs1 += __shfl_xor_sync(0xffffffffu, rs1, 2);
        l0 = l0 * a0 + rs0;
        l1 = l1 * a1 + rs1;

#pragma unroll
        for (int dt = 0; dt < 8; dt++) {
            o[dt][0] *= a0; o[dt][1] *= a0;
            o[dt][2] *= a1; o[dt][3] *= a1;
        }

        // ---- O += P V : pack P fragments from S regs per k16 chunk ----
#pragma unroll
        for (int kc = 0; kc < 8; kc++) {
            const int nt0 = 2 * kc, nt1 = 2 * kc + 1;
            uint32_t ah[4], al[4];
            split2(s[nt0][0], s[nt0][1], ah[0], al[0]);
            split2(s[nt0][2], s[nt0][3], ah[1], al[1]);
            split2(s[nt1][0], s[nt1][1], ah[2], al[2]);
            split2(s[nt1][2], s[nt1][3], ah[3], al[3]);
#pragma unroll
            for (int dt = 0; dt < 8; dt++) {
                const int vr0 = (8 * kc + t) * FVS + dt * 8 + g;
                const int vr1 = (8 * kc + t + 4) * FVS + dt * 8 + g;
                uint32_t bh[2] = { Vh[vr0], Vh[vr1] };
                uint32_t bl[2] = { Vl[vr0], Vl[vr1] };
                mma_bf16(o[dt], ah, bh);
                mma_bf16(o[dt], ah, bl);
                mma_bf16(o[dt], al, bh);
            }
        }
    }

    // ---- normalize + write out ----
    const float inv0 = 1.0f / l0;
    const float inv1 = 1.0f / l1;
#pragma unroll
    for (int dt = 0; dt < 8; dt++) {
        int col = h * HDIM + dt * 8 + 2 * t;
        *(float2*)&O[(size_t)(b * SEQ + R0g) * DMODEL + col] =
            make_float2(o[dt][0] * inv0, o[dt][1] * inv0);
        *(float2*)&O[(size_t)(b * SEQ + R1g) * DMODEL + col] =
            make_float2(o[dt][2] * inv1, o[dt][3] * inv1);
    }
}

// ---------------------------------------------------------------------------
// Launch
// ---------------------------------------------------------------------------
extern "C" void kernel_launch(void* const* d_in, const int* in_sizes, int n_in,
                              void* d_out, int out_size)
{
    const float* x  = (const float*)d_in[0];
    const float* Wq = (const float*)d_in[1];
    const float* Wk = (const float*)d_in[2];
    const float* Wv = (const float*)d_in[3];
    const float* Wo = (const float*)d_in[4];
    float* out = (float*)d_out;

    float* scratch = nullptr;
    cudaGetSymbolAddress((void**)&scratch, g_scratch);
    const size_t PLANE = (size_t)MTOT * DMODEL;
    float* Qb = scratch;
    float* Kb = scratch + PLANE;
    float* Vb = scratch + 2 * PLANE;
    float* Ab = scratch + 3 * PLANE;

    dim3 ggrid(DMODEL / 128, MTOT / 128);   // (8, 64)
    gemm_nt_bf16_kernel<<<ggrid, 256>>>(x, Wq, Qb, MTOT, DMODEL, DMODEL);
    gemm_nt_bf16_kernel<<<ggrid, 256>>>(x, Wk, Kb, MTOT, DMODEL, DMODEL);
    gemm_nt_bf16_kernel<<<ggrid, 256>>>(x, Wv, Vb, MTOT, DMODEL, DMODEL);

    int smem_bytes = (4 * 128 * FQS + 2 * 64 * FVS) * (int)sizeof(uint32_t);  // 108544
    cudaFuncSetAttribute(flash_tc_kernel, cudaFuncAttributeMaxDynamicSharedMemorySize, smem_bytes);
    flash_tc_kernel<<<dim3(SEQ / 128, BATCH * NHEADS), 256, smem_bytes>>>(Qb, Kb, Vb, Ab);

    gemm_nt_bf16_kernel<<<ggrid, 256>>>(Ab, Wo, out, MTOT, DMODEL, DMODEL);
}